// round 1
// baseline (speedup 1.0000x reference)
#include <cuda_runtime.h>
#include <math.h>

// Histogram2D: N=500k points (row-major [N,6] fp32, only cols 0,1 used),
// 128x128 bins over [-3,3]^2, Gaussian-CDF (erf) smoothing with bandwidth =
// one bin width, output normalized to a probability density (fp32 128x128).
//
// Strategy: each point's weight support is ~±5 bins (erfc(5/sqrt2) ~ 5e-7),
// so scatter a 12x16 rank-1 patch into a per-CTA private shared-memory
// histogram with shared atomics; flush CTA histograms into a __device__
// global accumulator with global atomics; final single-block kernel sums and
// normalizes into d_out.

#define NB      128          // bins per axis
#define RX      12           // x (row) window: covers cx-5 .. cx+6
#define CY      16           // y (col) window: aligned, covers >= cy-6 .. cy+6
#define SHS     132          // padded shared row stride (floats)
#define THREADS 256
#define BLOCKS  444          // 3 CTAs per SM on 148 SMs

__device__ float g_hist[NB * NB];

__global__ void zero_kernel() {
    int i = blockIdx.x * blockDim.x + threadIdx.x;
    if (i < NB * NB) g_hist[i] = 0.0f;
}

__global__ __launch_bounds__(THREADS, 3)
void hist_kernel(const float* __restrict__ x,
                 const float* __restrict__ ex,
                 const float* __restrict__ ey,
                 int n)
{
    extern __shared__ float sh[];

    // zero the private histogram
    for (int i = threadIdx.x; i < NB * SHS; i += THREADS) sh[i] = 0.0f;
    __syncthreads();

    const float lo     = __ldg(&ex[0]);
    const float dx     = __ldg(&ex[1]) - lo;
    const float inv_dx = 1.0f / dx;
    // 1 / (bw * sqrt(2)), bw = BANDWIDTH * dx with BANDWIDTH = 1
    const float invb   = inv_dx * 0.7071067811865475f;

    for (int p = blockIdx.x * THREADS + threadIdx.x; p < n;
         p += gridDim.x * THREADS)
    {
        const float u = __ldg(&x[p * 6 + 0]);
        const float v = __ldg(&x[p * 6 + 1]);

        int cx = (int)floorf((u - lo) * inv_dx);
        cx = min(max(cx, 0), NB - 1);
        int sx = min(max(cx - 5, 0), NB - RX);

        int cy = (int)floorf((v - lo) * inv_dx);
        cy = min(max(cy, 0), NB - 1);
        int sy = min(max((cy - 6) & ~3, 0), NB - CY);

        // per-point Gaussian mass per bin via erf differences (exact edges)
        float wx[RX];
        {
            float prev = erff((__ldg(&ex[sx]) - u) * invb);
#pragma unroll
            for (int k = 0; k < RX; k++) {
                float nx = erff((__ldg(&ex[sx + k + 1]) - u) * invb);
                wx[k] = 0.5f * (nx - prev);
                prev = nx;
            }
        }
        float wy[CY];
        {
            float prev = erff((__ldg(&ey[sy]) - v) * invb);
#pragma unroll
            for (int k = 0; k < CY; k++) {
                float nx = erff((__ldg(&ey[sy + k + 1]) - v) * invb);
                wy[k] = 0.5f * (nx - prev);
                prev = nx;
            }
        }

        // scatter the rank-1 patch
#pragma unroll
        for (int i = 0; i < RX; i++) {
            float wxi = wx[i];
            float* row = &sh[(sx + i) * SHS + sy];
#pragma unroll
            for (int j = 0; j < CY; j++)
                atomicAdd(&row[j], wxi * wy[j]);
        }
    }

    __syncthreads();

    // flush private histogram to global accumulator (skip zero quads)
    for (int q = threadIdx.x; q < NB * NB / 4; q += THREADS) {
        int r = q >> 5;            // (q*4) / 128
        int c = (q & 31) << 2;     // (q*4) % 128
        float4 v4 = *reinterpret_cast<const float4*>(&sh[r * SHS + c]);
        if (v4.x != 0.0f || v4.y != 0.0f || v4.z != 0.0f || v4.w != 0.0f) {
            atomicAdd(&g_hist[r * NB + c + 0], v4.x);
            atomicAdd(&g_hist[r * NB + c + 1], v4.y);
            atomicAdd(&g_hist[r * NB + c + 2], v4.z);
            atomicAdd(&g_hist[r * NB + c + 3], v4.w);
        }
    }
}

__global__ void norm_kernel(const float* __restrict__ ex,
                            float* __restrict__ out)
{
    __shared__ float red[THREADS];
    __shared__ float s_scale;

    float s = 0.0f;
    for (int i = threadIdx.x; i < NB * NB; i += THREADS) s += g_hist[i];
    red[threadIdx.x] = s;
    __syncthreads();
    for (int off = THREADS / 2; off > 0; off >>= 1) {
        if (threadIdx.x < off) red[threadIdx.x] += red[threadIdx.x + off];
        __syncthreads();
    }
    if (threadIdx.x == 0) {
        float dx = ex[1] - ex[0];
        s_scale = 1.0f / (red[0] * dx * dx);
    }
    __syncthreads();
    for (int i = threadIdx.x; i < NB * NB; i += THREADS)
        out[i] = g_hist[i] * s_scale;
}

extern "C" void kernel_launch(void* const* d_in, const int* in_sizes, int n_in,
                              void* d_out, int out_size)
{
    const float* x  = (const float*)d_in[0];
    const float* ex = (const float*)d_in[1];
    const float* ey = (const float*)d_in[2];
    float* out = (float*)d_out;
    int n = in_sizes[0] / 6;

    cudaFuncSetAttribute(hist_kernel,
                         cudaFuncAttributeMaxDynamicSharedMemorySize,
                         NB * SHS * (int)sizeof(float));

    zero_kernel<<<(NB * NB + 255) / 256, 256>>>();
    hist_kernel<<<BLOCKS, THREADS, NB * SHS * sizeof(float)>>>(x, ex, ey, n);
    norm_kernel<<<1, THREADS>>>(ex, out);
}

// round 2
// speedup vs baseline: 1.2789x; 1.2789x over previous
#include <cuda_runtime.h>
#include <math.h>

// Histogram2D: N=500k points ([N,6] fp32, cols 0,1), 128x128 bins on [-3,3]^2,
// Gaussian-CDF (erf) smoothing, bandwidth = 1 bin; output normalized density.
//
// R2: 11x11 patch (±5 bins, tail ~2e-7), SHS=129 + unaligned sy for full
// 32-bank spread of shared atomics, arithmetic edges (no edge LDGs),
// non-atomic flush to per-CTA partials + coalesced tree reduce.

#define NB      128
#define W       11           // window bins per axis (covers +/-5 around point)
#define SHS     129          // shared row stride (odd => full bank spread)
#define THREADS 256
#define BLOCKS  444          // 3 CTAs/SM * 148 SMs
#define RBLK    64           // reduce-kernel blocks (64*256 = 16384 bins)

__device__ float g_part[BLOCKS * NB * NB];   // per-CTA partial histograms
__device__ float g_hist[NB * NB];
__device__ float g_bsum[RBLK];

__global__ void zero_kernel() {               // trivial; keeps launch indexing
    if (threadIdx.x < RBLK) g_bsum[threadIdx.x] = 0.0f;
}

__global__ __launch_bounds__(THREADS, 3)
void hist_kernel(const float* __restrict__ x,
                 const float* __restrict__ ex,
                 int n)
{
    extern __shared__ float sh[];

    for (int i = threadIdx.x; i < NB * SHS; i += THREADS) sh[i] = 0.0f;
    __syncthreads();

    const float lo     = __ldg(&ex[0]);
    const float dx     = __ldg(&ex[1]) - lo;
    const float inv_dx = 1.0f / dx;
    const float c      = 0.7071067811865475f;   // edge->erf arg scale (bins)

    for (int p = blockIdx.x * THREADS + threadIdx.x; p < n;
         p += gridDim.x * THREADS)
    {
        const float u = __ldg(&x[p * 6 + 0]);
        const float v = __ldg(&x[p * 6 + 1]);

        const float tu = (u - lo) * inv_dx;     // position in bin units
        const float tv = (v - lo) * inv_dx;

        int sx = (int)floorf(tu) - 5;
        sx = min(max(sx, 0), NB - W);
        int sy = (int)floorf(tv) - 5;
        sy = min(max(sy, 0), NB - W);

        // Gaussian mass per bin via erf differences; edges arithmetic:
        // arg_k = ((sx+k) - t) / sqrt(2)
        float wx[W];
        {
            float a    = ((float)sx - tu) * c;
            float prev = erff(a);
#pragma unroll
            for (int k = 0; k < W; k++) {
                float nx = erff(a + (float)(k + 1) * c);
                wx[k] = 0.5f * (nx - prev);
                prev = nx;
            }
        }
        float wy[W];
        {
            float a    = ((float)sy - tv) * c;
            float prev = erff(a);
#pragma unroll
            for (int k = 0; k < W; k++) {
                float nx = erff(a + (float)(k + 1) * c);
                wy[k] = 0.5f * (nx - prev);
                prev = nx;
            }
        }

        // scatter the rank-1 patch (addresses spread over all 32 banks)
#pragma unroll
        for (int i = 0; i < W; i++) {
            float wxi = wx[i];
            float* row = &sh[(sx + i) * SHS + sy];
#pragma unroll
            for (int j = 0; j < W; j++)
                atomicAdd(&row[j], wxi * wy[j]);
        }
    }

    __syncthreads();

    // non-atomic flush: full slab copy, coalesced
    float* dst = &g_part[blockIdx.x * (NB * NB)];
    for (int i = threadIdx.x; i < NB * NB; i += THREADS)
        dst[i] = sh[(i >> 7) * SHS + (i & 127)];
}

__global__ void reduce_kernel()
{
    __shared__ float red[THREADS];
    int b = blockIdx.x * THREADS + threadIdx.x;   // bin id, 64*256 = 16384

    float s = 0.0f;
#pragma unroll 4
    for (int cta = 0; cta < BLOCKS; cta++)
        s += g_part[cta * (NB * NB) + b];
    g_hist[b] = s;

    red[threadIdx.x] = s;
    __syncthreads();
    for (int off = THREADS / 2; off > 0; off >>= 1) {
        if (threadIdx.x < off) red[threadIdx.x] += red[threadIdx.x + off];
        __syncthreads();
    }
    if (threadIdx.x == 0) g_bsum[blockIdx.x] = red[0];
}

__global__ void norm_kernel(const float* __restrict__ ex,
                            float* __restrict__ out)
{
    __shared__ float red[RBLK];
    __shared__ float s_scale;

    if (threadIdx.x < RBLK) red[threadIdx.x] = g_bsum[threadIdx.x];
    __syncthreads();
    if (threadIdx.x == 0) {
        float tot = 0.0f;
        for (int i = 0; i < RBLK; i++) tot += red[i];
        float dx = ex[1] - ex[0];
        s_scale = 1.0f / (tot * dx * dx);
    }
    __syncthreads();
    float sc = s_scale;
    for (int i = threadIdx.x; i < NB * NB; i += THREADS)
        out[i] = g_hist[i] * sc;
}

extern "C" void kernel_launch(void* const* d_in, const int* in_sizes, int n_in,
                              void* d_out, int out_size)
{
    const float* x  = (const float*)d_in[0];
    const float* ex = (const float*)d_in[1];
    float* out = (float*)d_out;
    int n = in_sizes[0] / 6;

    cudaFuncSetAttribute(hist_kernel,
                         cudaFuncAttributeMaxDynamicSharedMemorySize,
                         NB * SHS * (int)sizeof(float));

    zero_kernel<<<1, 64>>>();
    hist_kernel<<<BLOCKS, THREADS, NB * SHS * sizeof(float)>>>(x, ex, n);
    reduce_kernel<<<RBLK, THREADS>>>();
    norm_kernel<<<1, THREADS>>>(ex, out);
}

// round 3
// speedup vs baseline: 2.5475x; 1.9919x over previous
#include <cuda_runtime.h>
#include <math.h>

// Histogram2D: N=500k points ([N,6] fp32, cols 0,1), 128x128 bins on [-3,3]^2,
// Gaussian-CDF (erf) smoothing (bw = 1 bin), output normalized density.
//
// R3: 512x9 fractional-position weight LUT (kills erf compute), W=9 window
// (81 shared atomics/pt), predicated boundary drop (matches reference
// out-of-grid truncation), parallel normalize, no zero kernel.

#define NB      128
#define W       9            // window bins per axis (+/-4 around point bin)
#define LUTN    512          // fractional-position quantization levels
#define LUTS    12           // LUT row stride (floats): 9 weights + pad
#define SHS     129          // shared hist row stride (odd -> full bank spread)
#define THREADS 256
#define BLOCKS  444          // 3 CTAs/SM * 148 SMs
#define RBLK    64

__device__ float g_lut[LUTN * LUTS];
__device__ float g_part[BLOCKS * NB * NB];
__device__ float g_hist[NB * NB];
__device__ float g_bsum[RBLK];

// Build weight LUT: row i = per-bin Gaussian masses for a point with
// fractional position f=(i+0.5)/LUTN inside its bin, window floor-4..floor+4.
__global__ void lut_kernel()
{
    int i = blockIdx.x * blockDim.x + threadIdx.x;
    if (i >= LUTN) return;
    const float c = 0.7071067811865475f;          // 1/sqrt(2), bin units
    float f = ((float)i + 0.5f) / (float)LUTN;
    float prev = erff((-4.0f - f) * c);
#pragma unroll
    for (int k = 0; k < W; k++) {
        float nx = erff(((float)(k - 3) - f) * c);
        g_lut[i * LUTS + k] = 0.5f * (nx - prev);
        prev = nx;
    }
#pragma unroll
    for (int k = W; k < LUTS; k++) g_lut[i * LUTS + k] = 0.0f;
}

__global__ __launch_bounds__(THREADS, 3)
void hist_kernel(const float* __restrict__ x,
                 const float* __restrict__ ex,
                 int n)
{
    extern __shared__ float sh[];

    for (int i = threadIdx.x; i < NB * SHS; i += THREADS) sh[i] = 0.0f;
    __syncthreads();

    const float lo     = __ldg(&ex[0]);
    const float inv_dx = 1.0f / (__ldg(&ex[1]) - lo);

    for (int p = blockIdx.x * THREADS + threadIdx.x; p < n;
         p += gridDim.x * THREADS)
    {
        const float2 uv = __ldg((const float2*)(x + p * 6));

        const float tu = (uv.x - lo) * inv_dx;    // position in bin units
        const float tv = (uv.y - lo) * inv_dx;
        const float fu = floorf(tu);
        const float fv = floorf(tv);

        const int sx = (int)fu - 4;               // window start (may be OOB)
        const int sy = (int)fv - 4;

        int lx = (int)((tu - fu) * (float)LUTN);  lx = min(lx, LUTN - 1);
        int ly = (int)((tv - fv) * (float)LUTN);  ly = min(ly, LUTN - 1);

        // fetch LUT rows (L1-resident): 2x float4 + 1 scalar per axis
        float wx[W], wy[W];
        {
            const float4* r = (const float4*)(g_lut + lx * LUTS);
            float4 a = __ldg(r), b = __ldg(r + 1);
            wx[0]=a.x; wx[1]=a.y; wx[2]=a.z; wx[3]=a.w;
            wx[4]=b.x; wx[5]=b.y; wx[6]=b.z; wx[7]=b.w;
            wx[8]=__ldg(g_lut + lx * LUTS + 8);
        }
        {
            const float4* r = (const float4*)(g_lut + ly * LUTS);
            float4 a = __ldg(r), b = __ldg(r + 1);
            wy[0]=a.x; wy[1]=a.y; wy[2]=a.z; wy[3]=a.w;
            wy[4]=b.x; wy[5]=b.y; wy[6]=b.z; wy[7]=b.w;
            wy[8]=__ldg(g_lut + ly * LUTS + 8);
        }

        // scatter rank-1 patch; out-of-grid bins dropped (matches reference)
#pragma unroll
        for (int i = 0; i < W; i++) {
            int bx = sx + i;
            if ((unsigned)bx < NB) {
                float wxi = wx[i];
                float* row = &sh[bx * SHS];
#pragma unroll
                for (int j = 0; j < W; j++) {
                    int by = sy + j;
                    if ((unsigned)by < NB)
                        atomicAdd(&row[by], wxi * wy[j]);
                }
            }
        }
    }

    __syncthreads();

    // non-atomic flush: coalesced slab copy
    float* dst = &g_part[blockIdx.x * (NB * NB)];
    for (int i = threadIdx.x; i < NB * NB; i += THREADS)
        dst[i] = sh[(i >> 7) * SHS + (i & 127)];
}

__global__ void reduce_kernel()
{
    __shared__ float red[THREADS];
    int b = blockIdx.x * THREADS + threadIdx.x;   // bin id (64*256 = 16384)

    float s = 0.0f;
#pragma unroll 4
    for (int cta = 0; cta < BLOCKS; cta++)
        s += g_part[cta * (NB * NB) + b];
    g_hist[b] = s;

    red[threadIdx.x] = s;
    __syncthreads();
    for (int off = THREADS / 2; off > 0; off >>= 1) {
        if (threadIdx.x < off) red[threadIdx.x] += red[threadIdx.x + off];
        __syncthreads();
    }
    if (threadIdx.x == 0) g_bsum[blockIdx.x] = red[0];
}

__global__ void norm_kernel(const float* __restrict__ ex,
                            float* __restrict__ out)
{
    float tot = 0.0f;
#pragma unroll
    for (int i = 0; i < RBLK; i++) tot += g_bsum[i];
    float dx = ex[1] - ex[0];
    float sc = 1.0f / (tot * dx * dx);

    int b = blockIdx.x * THREADS + threadIdx.x;
    out[b] = g_hist[b] * sc;
}

extern "C" void kernel_launch(void* const* d_in, const int* in_sizes, int n_in,
                              void* d_out, int out_size)
{
    const float* x  = (const float*)d_in[0];
    const float* ex = (const float*)d_in[1];
    float* out = (float*)d_out;
    int n = in_sizes[0] / 6;

    cudaFuncSetAttribute(hist_kernel,
                         cudaFuncAttributeMaxDynamicSharedMemorySize,
                         NB * SHS * (int)sizeof(float));

    lut_kernel<<<2, 256>>>();
    hist_kernel<<<BLOCKS, THREADS, NB * SHS * sizeof(float)>>>(x, ex, n);
    reduce_kernel<<<RBLK, THREADS>>>();
    norm_kernel<<<RBLK, THREADS>>>(ex, out);
}

// round 9
// speedup vs baseline: 3.8125x; 1.4966x over previous
#include <cuda_runtime.h>
#include <cuda_fp16.h>
#include <math.h>
#include <stdint.h>

// Histogram2D as GEMM on mma.sync (sm_80 PTX -> compiles at compute_103):
// per 128-point chunk build f16 tiles
//   A[m][k] = wx weight of point k at x-bin m   (128x128, 256B rows, XOR swz)
//   B[n][k] = wy weight of point k at y-bin n
// and accumulate D += A.B^T with m16n8k16 HMMA into per-warp fp32 registers.
// Each point owns one k-column -> weight scatter is race-free STS.16.
// R7 fix: B fragment must be loaded with NON-trans ldmatrix ([n][k] tile is
// already col-major KxN); R6's .trans transposed each 8x8 block (rel_err 8e-2).

#define NB      128
#define W       9            // +/-4 bin window per axis
#define LROWS   9728         // LUT: g = tpos - s0 + 5 in [0,19), 512 steps/bin
#define THREADS 256
#define CTAS    148
#define RBLK    64
#define TILE    32768        // one 128x128 f16 tile (256B per bin-row)

__device__ __align__(16) uint32_t g_lut[LROWS * 8];  // 16 halves/row (9 used)
__device__ float g_part[CTAS * NB * NB];
__device__ float g_hist[NB * NB];
__device__ float g_bsum[RBLK];

// ---------------- helpers ----------------
__device__ __forceinline__ uint32_t smem_u32(const void* p) {
    uint32_t a;
    asm("{ .reg .u64 t; cvta.to.shared.u64 t, %1; cvt.u32.u64 %0, t; }"
        : "=r"(a) : "l"(p));
    return a;
}
__device__ __forceinline__ void ldm_x4(uint32_t* r, uint32_t addr) {
    asm volatile("ldmatrix.sync.aligned.m8n8.x4.shared.b16 {%0,%1,%2,%3}, [%4];"
        : "=r"(r[0]), "=r"(r[1]), "=r"(r[2]), "=r"(r[3]) : "r"(addr));
}
__device__ __forceinline__ void mma16816(float* c, const uint32_t* a,
                                         const uint32_t* b) {
    asm volatile("mma.sync.aligned.m16n8k16.row.col.f32.f16.f16.f32 "
        "{%0,%1,%2,%3}, {%4,%5,%6,%7}, {%8,%9}, {%0,%1,%2,%3};"
        : "+f"(c[0]), "+f"(c[1]), "+f"(c[2]), "+f"(c[3])
        : "r"(a[0]), "r"(a[1]), "r"(a[2]), "r"(a[3]), "r"(b[0]), "r"(b[1]));
}

// write 9 halves (or zeros) into column k of a tile.
// byte(m,k) = m*256 + ((k>>3) ^ (m&7))*16 + (k&7)*2  (swizzle for ldmatrix)
__device__ __forceinline__ void put9(char* tile, int k, int s0,
                                     const uint32_t* r) {
    const uint32_t kc = (uint32_t)k >> 3;
    const uint32_t kw = ((uint32_t)k & 7) << 1;
#pragma unroll
    for (int j = 0; j < W; j++) {
        uint32_t m = (uint32_t)(s0 + j);
        uint32_t b = (m << 8) + (((kc ^ (m & 7)) << 4) | kw);
        uint16_t v = r ? (uint16_t)(r[j >> 1] >> ((j & 1) << 4)) : (uint16_t)0;
        *(uint16_t*)(tile + b) = v;
    }
}

// ---------------- kernels ----------------
__global__ void lut_kernel() {
    int i = blockIdx.x * blockDim.x + threadIdx.x;
    if (i >= LROWS) return;
    const float c = 0.7071067811865475f;
    float g = ((float)i + 0.5f) / 512.0f - 5.0f;   // point pos minus window start
    uint32_t out[8] = {0, 0, 0, 0, 0, 0, 0, 0};
    float prev = erff((0.0f - g) * c);
#pragma unroll
    for (int j = 0; j < W; j++) {
        float nx = erff(((float)(j + 1) - g) * c);
        uint32_t h = (uint32_t)__half_as_ushort(__float2half_rn(0.5f * (nx - prev)));
        out[j >> 1] |= h << ((j & 1) << 4);
        prev = nx;
    }
    uint4* dst = (uint4*)&g_lut[i * 8];
    dst[0] = make_uint4(out[0], out[1], out[2], out[3]);
    dst[1] = make_uint4(out[4], out[5], out[6], out[7]);
}

__global__ __launch_bounds__(THREADS, 1)
void hist_kernel(const float* __restrict__ x, const float* __restrict__ ex,
                 int n, int nch)
{
    extern __shared__ char sm[];                 // [A 32K][B 32K]
    const uint32_t smb = smem_u32(sm);
    const int tid  = threadIdx.x;
    const int lane = tid & 31;
    const int wrp  = tid >> 5;
    const int t    = tid & 127;                  // point slot within chunk
    const int mat  = tid >> 7;                   // 0: A (x), 1: B (y)
    const int cta  = blockIdx.x;

    for (int i = tid; i < (2 * TILE) / 16; i += THREADS)
        ((uint4*)sm)[i] = make_uint4(0, 0, 0, 0);

    const float lo     = __ldg(&ex[0]);
    const float inv_dx = 1.0f / (__ldg(&ex[1]) - lo);

    // warp-tile: 32 rows (m) x 64 cols (n)
    const int m_base = (wrp & 3) * 32;
    const int n_base = (wrp >> 2) * 64;
    const int lt = lane >> 3, l7 = lane & 7;
    const int a_hi = lt >> 1;                    // A k-chunk half
    const int a_m0 = m_base + (lt & 1) * 8 + l7;
    const int b_hi = lt & 1;                     // B k-chunk half
    const int b_n0 = n_base + (lt >> 1) * 8 + l7;

    float acc[2][8][4];
#pragma unroll
    for (int i = 0; i < 2; i++)
#pragma unroll
        for (int j = 0; j < 8; j++)
#pragma unroll
            for (int q = 0; q < 4; q++) acc[i][j][q] = 0.0f;

    char* mytile = sm + mat * TILE;
    int prev = 0;
    __syncthreads();

    for (int i = 0; i < nch; i++) {
        // ---- fill: clear previous column entries, write this chunk's point
        put9(mytile, t, prev, (const uint32_t*)0);
        int p = (cta + i * CTAS) * 128 + t;
        if (p < n) {
            float coord = __ldg(&x[p * 6 + mat]);
            float tp = (coord - lo) * inv_dx;
            int s0 = (int)floorf(tp) - 4;
            s0 = min(max(s0, 0), NB - W);
            int li = (int)((tp - (float)s0 + 5.0f) * 512.0f);
            li = min(max(li, 0), LROWS - 1);
            uint32_t r[6];
            const uint4 ra = *(const uint4*)&g_lut[li * 8];
            const uint2 rb = *(const uint2*)&g_lut[li * 8 + 4];
            r[0] = ra.x; r[1] = ra.y; r[2] = ra.z; r[3] = ra.w;
            r[4] = rb.x; r[5] = rb.y;
            put9(mytile, t, s0, r);
            prev = s0;
        }
        __syncthreads();

        // ---- MMA over this chunk's K=128
#pragma unroll
        for (int ks = 0; ks < 8; ks++) {
            uint32_t af0[4], af1[4];
            const uint32_t swa = (uint32_t)(((ks * 2 + a_hi) ^ l7) << 4);
            ldm_x4(af0, smb + (uint32_t)a_m0 * 256 + swa);
            ldm_x4(af1, smb + (uint32_t)(a_m0 + 16) * 256 + swa);
            const uint32_t swb = (uint32_t)(((ks * 2 + b_hi) ^ l7) << 4);
#pragma unroll
            for (int nt2 = 0; nt2 < 4; nt2++) {
                uint32_t bf[4];
                ldm_x4(bf, smb + TILE + (uint32_t)(b_n0 + nt2 * 16) * 256 + swb);
                mma16816(acc[0][nt2 * 2 + 0], af0, bf);
                mma16816(acc[0][nt2 * 2 + 1], af0, bf + 2);
                mma16816(acc[1][nt2 * 2 + 0], af1, bf);
                mma16816(acc[1][nt2 * 2 + 1], af1, bf + 2);
            }
        }
        __syncthreads();
    }

    // ---- readout: per-warp D tile -> per-CTA partial
    float* dst = g_part + cta * (NB * NB);
    const int col0 = (lane & 3) * 2;
#pragma unroll
    for (int mt = 0; mt < 2; mt++) {
        int row = m_base + mt * 16 + (lane >> 2);
#pragma unroll
        for (int nt = 0; nt < 8; nt++) {
            int col = n_base + nt * 8 + col0;
            *(float2*)&dst[row * NB + col] =
                make_float2(acc[mt][nt][0], acc[mt][nt][1]);
            *(float2*)&dst[(row + 8) * NB + col] =
                make_float2(acc[mt][nt][2], acc[mt][nt][3]);
        }
    }
}

__global__ void reduce_kernel()
{
    __shared__ float red[THREADS];
    int bin = blockIdx.x * THREADS + threadIdx.x;
    float s = 0.0f;
#pragma unroll 4
    for (int cta = 0; cta < CTAS; cta++)
        s += g_part[cta * (NB * NB) + bin];
    g_hist[bin] = s;

    red[threadIdx.x] = s;
    __syncthreads();
    for (int off = THREADS / 2; off > 0; off >>= 1) {
        if (threadIdx.x < off) red[threadIdx.x] += red[threadIdx.x + off];
        __syncthreads();
    }
    if (threadIdx.x == 0) g_bsum[blockIdx.x] = red[0];
}

__global__ void norm_kernel(const float* __restrict__ ex,
                            float* __restrict__ out)
{
    float tot = 0.0f;
#pragma unroll
    for (int i = 0; i < RBLK; i++) tot += g_bsum[i];
    float dx = ex[1] - ex[0];
    float sc = 1.0f / (tot * dx * dx);
    int b = blockIdx.x * THREADS + threadIdx.x;
    out[b] = g_hist[b] * sc;
}

extern "C" void kernel_launch(void* const* d_in, const int* in_sizes, int n_in,
                              void* d_out, int out_size)
{
    const float* x  = (const float*)d_in[0];
    const float* ex = (const float*)d_in[1];
    float* out = (float*)d_out;
    int n = in_sizes[0] / 6;
    int chunks = (n + 127) / 128;
    int nch = (chunks + CTAS - 1) / CTAS;
    if (nch < 1) nch = 1;

    cudaFuncSetAttribute(hist_kernel,
                         cudaFuncAttributeMaxDynamicSharedMemorySize, 2 * TILE);

    lut_kernel<<<(LROWS + 255) / 256, 256>>>();
    hist_kernel<<<CTAS, THREADS, 2 * TILE>>>(x, ex, n, nch);
    reduce_kernel<<<RBLK, THREADS>>>();
    norm_kernel<<<RBLK, THREADS>>>(ex, out);
}